// round 1
// baseline (speedup 1.0000x reference)
#include <cuda_runtime.h>
#include <math.h>

#define Bn 4
#define Cn 64
#define Hn 128
#define Wn 128
#define Pn 63
#define HW (Hn*Wn)

// Scratch (static device globals — no runtime allocation)
__device__ float g_a0[Bn*Cn*HW];   // act(c0)
__device__ float g_g0[Bn*Cn*HW];   // grad-act(c0)
__device__ float g_a1[Bn*HW];      // act(c1)
__device__ float g_d [Bn*Cn*HW];   // deconv1(a1) * g0

// 11-tap truncated Gaussian-mixture RBF: act = sum_p exp(-(v-m_p)^2/200)*w[p],
// m_p = -310 + 10p. u = v/10 + 31; only |u-p| <= 5.5 taps matter (>5.5 -> e^-15).
__device__ __forceinline__ void rbf_eval(float v, const float* __restrict__ wrow,
                                         float& a_out, float& g_out) {
    float u  = fmaf(v, 0.1f, 31.0f);
    float pf = rintf(u);
    pf = fminf(fmaxf(pf, 5.0f), 57.0f);   // keep window [pc-5,pc+5] inside [0,62]
    int   pc = (int)pf;
    float s  = u - pf;
    float a = 0.f, g = 0.f;
    #pragma unroll
    for (int j = -5; j <= 5; ++j) {
        float t  = s - (float)j;           // (v - m_p)/10
        float e  = __expf(-0.5f * t * t);  // underflows safely for huge |v|
        float we = wrow[pc + j] * e;
        a += we;
        g  = fmaf(we, t, g);
    }
    a_out = a;
    g_out = -0.1f * g;                     // grad factor d/(-100) = 10t/(-100)
}

// K1: c0 = conv5x5(rep_pad(255*x), f0)+b0 ; a0 = act(c0,w0); g0 = gradact(c0,w0)
__global__ void k1_conv0_act(const float* __restrict__ x,
                             const float* __restrict__ f0,
                             const float* __restrict__ b0,
                             const float* __restrict__ w0) {
    __shared__ float sf0[Cn*25];
    __shared__ float sb0[Cn];
    __shared__ float sw0[Cn*Pn];
    int tid = threadIdx.x;
    for (int i = tid; i < Cn*25; i += 256) sf0[i] = f0[i];
    for (int i = tid; i < Cn;    i += 256) sb0[i] = b0[i];
    for (int i = tid; i < Cn*Pn; i += 256) sw0[i] = w0[i];
    __syncthreads();

    int b = blockIdx.z;
    int cbase = blockIdx.y * 16;
    int p = blockIdx.x * 256 + tid;
    int h = p >> 7, w = p & 127;
    const float* xb = x + b*HW;

    float xn[25];
    #pragma unroll
    for (int dy = 0; dy < 5; ++dy) {
        int ih = min(max(h + dy - 2, 0), Hn-1);
        #pragma unroll
        for (int dx = 0; dx < 5; ++dx) {
            int iw = min(max(w + dx - 2, 0), Wn-1);
            xn[dy*5+dx] = xb[ih*Wn + iw] * 255.0f;
        }
    }
    #pragma unroll 4
    for (int cc = 0; cc < 16; ++cc) {
        int c = cbase + cc;
        float acc = sb0[c];
        const float* fr = &sf0[c*25];
        #pragma unroll
        for (int k = 0; k < 25; ++k) acc = fmaf(xn[k], fr[k], acc);
        float a, g;
        rbf_eval(acc, &sw0[c*Pn], a, g);
        int idx = (b*Cn + c)*HW + p;
        g_a0[idx] = a;
        g_g0[idx] = g;
    }
}

#define TCH 8
// K2: c1 = conv5x5(rep_pad(a0), f1)+b1 (64->1); a1 = act(c1, w1)
__global__ void k2_conv1_act(const float* __restrict__ f1,
                             const float* __restrict__ b1,
                             const float* __restrict__ w1) {
    __shared__ float tile[TCH][20][20];
    __shared__ float sf1[Cn*25];
    __shared__ float sw1[Pn];
    int tx = threadIdx.x, ty = threadIdx.y;
    int tid = ty*16 + tx;
    for (int i = tid; i < Cn*25; i += 256) sf1[i] = f1[i];
    if (tid < Pn) sw1[tid] = w1[tid];

    int b = blockIdx.z;
    int h0 = blockIdx.y * 16, w0b = blockIdx.x * 16;
    float acc = 0.f;
    for (int cc = 0; cc < Cn; cc += TCH) {
        __syncthreads();
        for (int i = tid; i < TCH*400; i += 256) {
            int ch = i / 400, rem = i % 400;
            int r = rem / 20, cx = rem % 20;
            int gh = min(max(h0 + r - 2, 0), Hn-1);
            int gw = min(max(w0b + cx - 2, 0), Wn-1);
            tile[ch][r][cx] = g_a0[(b*Cn + cc + ch)*HW + gh*Wn + gw];
        }
        __syncthreads();
        #pragma unroll
        for (int ch = 0; ch < TCH; ++ch) {
            const float* fr = &sf1[(cc+ch)*25];
            #pragma unroll
            for (int ky = 0; ky < 5; ++ky)
                #pragma unroll
                for (int kx = 0; kx < 5; ++kx)
                    acc = fmaf(tile[ch][ty+ky][tx+kx], fr[ky*5+kx], acc);
        }
    }
    acc += b1[0];
    float a, g;
    rbf_eval(acc, sw1, a, g);
    g_a1[b*HW + (h0+ty)*Wn + (w0b+tx)] = a;
}

// K3: d = crop(conv_transpose(a1, f1)) * g0  (1->64, zero pad, flipped f1)
__global__ void k3_deconv1(const float* __restrict__ f1) {
    __shared__ float sf1f[Cn*25];
    int tid = threadIdx.x;
    for (int i = tid; i < Cn*25; i += 256) {
        int c = i / 25, k = i % 25;
        sf1f[c*25 + k] = f1[c*25 + (24 - k)];  // spatial flip
    }
    __syncthreads();

    int b = blockIdx.z;
    int cbase = blockIdx.y * 16;
    int p = blockIdx.x * 256 + tid;
    int h = p >> 7, w = p & 127;
    const float* ab = g_a1 + b*HW;

    float an[25];
    #pragma unroll
    for (int dy = 0; dy < 5; ++dy) {
        int ih = h + dy - 2;
        #pragma unroll
        for (int dx = 0; dx < 5; ++dx) {
            int iw = w + dx - 2;
            an[dy*5+dx] = (ih >= 0 && ih < Hn && iw >= 0 && iw < Wn)
                          ? ab[ih*Wn + iw] : 0.f;
        }
    }
    #pragma unroll 4
    for (int cc = 0; cc < 16; ++cc) {
        int c = cbase + cc;
        float acc = 0.f;
        const float* fr = &sf1f[c*25];
        #pragma unroll
        for (int k = 0; k < 25; ++k) acc = fmaf(an[k], fr[k], acc);
        int idx = (b*Cn + c)*HW + p;
        g_d[idx] = acc * g_g0[idx];
    }
}

// K4: d2 = crop(conv_transpose(d, f0)) (64->1, zero pad, flipped f0)
//     out = x - d2/255 - exp(lam_param)*(x - y)
__global__ void k4_deconv0_out(const float* __restrict__ x,
                               const float* __restrict__ y,
                               const float* __restrict__ f0,
                               const float* __restrict__ lam_param,
                               float* __restrict__ out) {
    __shared__ float tile[TCH][20][20];
    __shared__ float sf0f[Cn*25];
    int tx = threadIdx.x, ty = threadIdx.y;
    int tid = ty*16 + tx;
    for (int i = tid; i < Cn*25; i += 256) {
        int c = i / 25, k = i % 25;
        sf0f[c*25 + k] = f0[c*25 + (24 - k)];
    }
    int b = blockIdx.z;
    int h0 = blockIdx.y * 16, w0b = blockIdx.x * 16;
    float acc = 0.f;
    for (int cc = 0; cc < Cn; cc += TCH) {
        __syncthreads();
        for (int i = tid; i < TCH*400; i += 256) {
            int ch = i / 400, rem = i % 400;
            int r = rem / 20, cx = rem % 20;
            int gh = h0 + r - 2, gw = w0b + cx - 2;
            float v = 0.f;
            if (gh >= 0 && gh < Hn && gw >= 0 && gw < Wn)
                v = g_d[(b*Cn + cc + ch)*HW + gh*Wn + gw];
            tile[ch][r][cx] = v;
        }
        __syncthreads();
        #pragma unroll
        for (int ch = 0; ch < TCH; ++ch) {
            const float* fr = &sf0f[(cc+ch)*25];
            #pragma unroll
            for (int ky = 0; ky < 5; ++ky)
                #pragma unroll
                for (int kx = 0; kx < 5; ++kx)
                    acc = fmaf(tile[ch][ty+ky][tx+kx], fr[ky*5+kx], acc);
        }
    }
    int pix = (h0+ty)*Wn + (w0b+tx);
    float xv = x[b*HW + pix];
    float yv = y[b*HW + pix];
    float e  = __expf(lam_param[0]);
    // (255x - (d2 + e*(255x-255y)))/255 = x - d2/255 - e*(x-y)
    out[b*HW + pix] = xv - acc*(1.0f/255.0f) - e*(xv - yv);
}

extern "C" void kernel_launch(void* const* d_in, const int* in_sizes, int n_in,
                              void* d_out, int out_size) {
    const float* x   = (const float*)d_in[0];
    const float* y   = (const float*)d_in[1];
    // d_in[2] = lam (ignored by the model)
    const float* f0  = (const float*)d_in[3];
    const float* b0  = (const float*)d_in[4];
    const float* f1  = (const float*)d_in[5];
    const float* b1  = (const float*)d_in[6];
    const float* w0  = (const float*)d_in[7];
    const float* w1  = (const float*)d_in[8];
    const float* lam = (const float*)d_in[9];
    float* out = (float*)d_out;

    dim3 g1(HW/256, Cn/16, Bn);
    dim3 g2(Wn/16, Hn/16, Bn), b2(16, 16);

    k1_conv0_act<<<g1, 256>>>(x, f0, b0, w0);
    k2_conv1_act<<<g2, b2>>>(f1, b1, w1);
    k3_deconv1 <<<g1, 256>>>(f1);
    k4_deconv0_out<<<g2, b2>>>(x, y, f0, lam, out);
}

// round 2
// speedup vs baseline: 1.3116x; 1.3116x over previous
#include <cuda_runtime.h>
#include <math.h>

#define Bn 4
#define Cn 64
#define Hn 128
#define Wn 128
#define Pn 63
#define HW (Hn*Wn)

// Scratch (static device globals)
__device__ float g_a0[Bn*Cn*HW];   // act(c0)
__device__ float g_g0[Bn*Cn*HW];   // grad-act(c0)
__device__ float g_a1[Bn*HW];      // act(c1)
__device__ float g_d [Bn*Cn*HW];   // deconv1(a1) * g0
__device__ float g_part[8*Bn*HW];  // channel-group partial sums (reused by K2/K4)

// Filters & biases in constant memory: warp-uniform indices -> LDCU (uniform pipe)
__constant__ float c_f0[Cn*25];
__constant__ float c_f1[Cn*25];
__constant__ float c_b0[Cn];
__constant__ float c_b1[1];

// 9-tap truncated Gaussian-mixture RBF. u = v/10 + 31; taps |u-p|<=4.5.
__device__ __forceinline__ void rbf9(float v, const float* __restrict__ wrow,
                                     float& a_out, float& g_out) {
    float u  = fmaf(v, 0.1f, 31.0f);
    float pf = rintf(u);
    pf = fminf(fmaxf(pf, 4.0f), 58.0f);   // window [pc-4,pc+4] stays in [0,62]
    int   pc = (int)pf;
    float s  = u - pf;
    float a = 0.f, g = 0.f;
    #pragma unroll
    for (int j = -4; j <= 4; ++j) {
        float t  = s - (float)j;           // (v - m_p)/10
        float e  = __expf(-0.5f * t * t);
        float we = wrow[pc + j] * e;
        a += we;
        g  = fmaf(we, t, g);
    }
    a_out = a;
    g_out = -0.1f * g;
}

// K1: c0 = conv5x5(rep_pad(255x), f0)+b0 ; a0 = act(c0,w0), g0 = gradact(c0,w0)
__global__ void k1_conv0_act(const float* __restrict__ x,
                             const float* __restrict__ w0) {
    __shared__ float sw0[16*63];
    int tid = threadIdx.x;
    int cbase = blockIdx.y * 16;
    for (int i = tid; i < 16*63; i += 256) sw0[i] = w0[cbase*63 + i];
    __syncthreads();

    int b = blockIdx.z;
    int p = blockIdx.x * 256 + tid;
    int h = p >> 7, w = p & 127;
    const float* xb = x + b*HW;

    float xn[25];
    #pragma unroll
    for (int dy = 0; dy < 5; ++dy) {
        int ih = min(max(h + dy - 2, 0), Hn-1);
        #pragma unroll
        for (int dx = 0; dx < 5; ++dx) {
            int iw = min(max(w + dx - 2, 0), Wn-1);
            xn[dy*5+dx] = xb[ih*Wn + iw] * 255.0f;
        }
    }
    #pragma unroll 1
    for (int cc = 0; cc < 16; ++cc) {
        int c = cbase + cc;
        float acc = c_b0[c];
        #pragma unroll
        for (int k = 0; k < 25; ++k) acc = fmaf(xn[k], c_f0[c*25 + k], acc);
        float a, g;
        rbf9(acc, &sw0[cc*63], a, g);
        int idx = (b*Cn + c)*HW + p;
        g_a0[idx] = a;
        g_g0[idx] = g;
    }
}

// 64->1 conv (channel-group partials). Each CTA: 64x16 output tile, 8 channels.
// Each thread: 1x4 output strip via register tiling (2x LDS.128 per row).
// SRC: 0 -> g_a0 (K2a, clamp/rep_pad, filter f1), 1 -> g_d (K4a, zero pad, flipped f0)
template<int SRC, bool FLIP_F0, bool CLAMP>
__global__ void conv64to1_part() {
    __shared__ float tile[20][68];
    int tid = threadIdx.x;
    int tx = tid & 15;          // 16 strips of 4 px
    int ty = tid >> 4;          // 16 rows
    int b  = blockIdx.z & 3;
    int g  = blockIdx.z >> 2;   // channel group 0..7
    int h0 = blockIdx.y * 16;
    int w0 = blockIdx.x * 64;
    const float* sb = (SRC == 0 ? g_a0 : g_d) + (size_t)(b*Cn + g*8)*HW;

    float acc0 = 0.f, acc1 = 0.f, acc2 = 0.f, acc3 = 0.f;

    #pragma unroll 1
    for (int cc = 0; cc < 8; ++cc) {
        __syncthreads();
        const float* sc = sb + cc*HW;
        for (int i = tid; i < 20*68; i += 256) {
            int r  = i / 68;
            int cx = i - r*68;
            int gh = h0 + r - 2, gw = w0 + cx - 2;
            float v;
            if (CLAMP) {
                gh = min(max(gh, 0), Hn-1);
                gw = min(max(gw, 0), Wn-1);
                v = sc[gh*Wn + gw];
            } else {
                v = ((unsigned)gh < (unsigned)Hn && (unsigned)gw < (unsigned)Wn)
                    ? sc[gh*Wn + gw] : 0.f;
            }
            (&tile[0][0])[i] = v;
        }
        __syncthreads();

        float rr[5][8];
        #pragma unroll
        for (int r = 0; r < 5; ++r) {
            float4 v0 = *(const float4*)&tile[ty + r][tx*4];
            float4 v1 = *(const float4*)&tile[ty + r][tx*4 + 4];
            rr[r][0] = v0.x; rr[r][1] = v0.y; rr[r][2] = v0.z; rr[r][3] = v0.w;
            rr[r][4] = v1.x; rr[r][5] = v1.y; rr[r][6] = v1.z; rr[r][7] = v1.w;
        }
        int c = g*8 + cc;
        #pragma unroll
        for (int ky = 0; ky < 5; ++ky) {
            #pragma unroll
            for (int kx = 0; kx < 5; ++kx) {
                float f = FLIP_F0 ? c_f0[c*25 + 24 - (ky*5 + kx)]
                                  : c_f1[c*25 + ky*5 + kx];
                acc0 = fmaf(rr[ky][kx+0], f, acc0);
                acc1 = fmaf(rr[ky][kx+1], f, acc1);
                acc2 = fmaf(rr[ky][kx+2], f, acc2);
                acc3 = fmaf(rr[ky][kx+3], f, acc3);
            }
        }
    }
    float4 o = make_float4(acc0, acc1, acc2, acc3);
    *(float4*)&g_part[(size_t)g*(Bn*HW) + b*HW + (h0+ty)*Wn + w0 + tx*4] = o;
}

// K2b: a1 = act(sum(partials) + b1, w1)
__global__ void k2b_reduce_act(const float* __restrict__ w1) {
    __shared__ float sw[Pn];
    int tid = threadIdx.x;
    if (tid < Pn) sw[tid] = w1[tid];
    __syncthreads();
    int p = blockIdx.x * 256 + tid;      // p in [0, Bn*HW)
    float s = c_b1[0];
    #pragma unroll
    for (int g = 0; g < 8; ++g) s += g_part[g*(Bn*HW) + p];
    float a, gr;
    rbf9(s, sw, a, gr);
    g_a1[p] = a;
}

// K3: d = crop(conv_transpose(a1, f1)) * g0  (1->64, zero pad, flipped f1)
__global__ void k3_deconv1() {
    int tid = threadIdx.x;
    int b = blockIdx.z;
    int cbase = blockIdx.y * 16;
    int p = blockIdx.x * 256 + tid;
    int h = p >> 7, w = p & 127;
    const float* ab = g_a1 + b*HW;

    float an[25];
    #pragma unroll
    for (int dy = 0; dy < 5; ++dy) {
        int ih = h + dy - 2;
        #pragma unroll
        for (int dx = 0; dx < 5; ++dx) {
            int iw = w + dx - 2;
            an[dy*5+dx] = ((unsigned)ih < (unsigned)Hn && (unsigned)iw < (unsigned)Wn)
                          ? ab[ih*Wn + iw] : 0.f;
        }
    }
    #pragma unroll 1
    for (int cc = 0; cc < 16; ++cc) {
        int c = cbase + cc;
        float acc = 0.f;
        #pragma unroll
        for (int k = 0; k < 25; ++k) acc = fmaf(an[k], c_f1[c*25 + 24 - k], acc);
        int idx = (b*Cn + c)*HW + p;
        g_d[idx] = acc * g_g0[idx];
    }
}

// K4b: out = x - sum(partials)/255 - exp(lam)*(x - y)
__global__ void k4b_reduce_out(const float* __restrict__ x,
                               const float* __restrict__ y,
                               const float* __restrict__ lam_param,
                               float* __restrict__ out) {
    int p = blockIdx.x * 256 + threadIdx.x;
    float s = 0.f;
    #pragma unroll
    for (int g = 0; g < 8; ++g) s += g_part[g*(Bn*HW) + p];
    float e  = __expf(lam_param[0]);
    float xv = x[p], yv = y[p];
    out[p] = xv - s*(1.0f/255.0f) - e*(xv - yv);
}

extern "C" void kernel_launch(void* const* d_in, const int* in_sizes, int n_in,
                              void* d_out, int out_size) {
    const float* x   = (const float*)d_in[0];
    const float* y   = (const float*)d_in[1];
    // d_in[2] = lam (ignored by the model)
    const float* f0  = (const float*)d_in[3];
    const float* b0  = (const float*)d_in[4];
    const float* f1  = (const float*)d_in[5];
    const float* b1  = (const float*)d_in[6];
    const float* w0  = (const float*)d_in[7];
    const float* w1  = (const float*)d_in[8];
    const float* lam = (const float*)d_in[9];
    float* out = (float*)d_out;

    cudaMemcpyToSymbolAsync(c_f0, f0, Cn*25*sizeof(float), 0, cudaMemcpyDeviceToDevice, 0);
    cudaMemcpyToSymbolAsync(c_f1, f1, Cn*25*sizeof(float), 0, cudaMemcpyDeviceToDevice, 0);
    cudaMemcpyToSymbolAsync(c_b0, b0, Cn*sizeof(float),    0, cudaMemcpyDeviceToDevice, 0);
    cudaMemcpyToSymbolAsync(c_b1, b1, sizeof(float),       0, cudaMemcpyDeviceToDevice, 0);

    dim3 gA(HW/256, Cn/16, Bn);        // (64, 4, 4) — per-pixel kernels
    dim3 gT(Wn/64, Hn/16, Bn*8);       // (2, 8, 32) — tiled 64->1 conv partials
    dim3 gR(Bn*HW/256);                // (256)      — reductions/epilogues

    k1_conv0_act<<<gA, 256>>>(x, w0);
    conv64to1_part<0, false, true ><<<gT, 256>>>();   // K2a: conv(a0, f1), rep-pad
    k2b_reduce_act<<<gR, 256>>>(w1);
    k3_deconv1<<<gA, 256>>>();
    conv64to1_part<1, true,  false><<<gT, 256>>>();   // K4a: deconv(d, flip f0), zero-pad
    k4b_reduce_out<<<gR, 256>>>(x, y, lam, out);
}

// round 3
// speedup vs baseline: 1.5821x; 1.2063x over previous
#include <cuda_runtime.h>
#include <math.h>

#define Bn 4
#define Cn 64
#define Hn 128
#define Wn 128
#define Pn 63
#define HW (Hn*Wn)

// Scratch (static device globals)
__device__ float g_a0[Bn*Cn*HW];   // act(c0)
__device__ float g_g0[Bn*Cn*HW];   // grad-act(c0)
__device__ float g_a1[Bn*HW];      // act(c1)
__device__ float g_part[8*Bn*HW];  // channel-group partial sums (reused by K2/K5)

__constant__ float c_f0[Cn*25];
__constant__ float c_f1[Cn*25];
__constant__ float c_b0[Cn];
__constant__ float c_b1[1];

__device__ __forceinline__ float ex2f_(float x){ float r; asm("ex2.approx.f32 %0,%1;" : "=f"(r) : "f"(x)); return r; }
__device__ __forceinline__ float rcpf_(float x){ float r; asm("rcp.approx.f32 %0,%1;" : "=f"(r) : "f"(x)); return r; }

#define CJ1 0.60653065971f      /* exp(-1/2)  */
#define CJ2 0.13533528324f      /* exp(-4/2)  */
#define CJ3 0.01110899654f      /* exp(-9/2)  */
#define CJ4 0.00033546262f      /* exp(-16/2) */
#define L2E 1.44269504089f

// 9-tap RBF via exp decomposition: exp(-(s-j)^2/2) = E0 * r^j * c_j
// a = E0 * sum_j w[pc+j] c_j r^j ;  g = -0.1 * E0 * (s*A - B), B = sum m_j*j
__device__ __forceinline__ void rbf9(float v, const float* __restrict__ w,
                                     float& a_out, float& g_out) {
    float u  = fmaf(v, 0.1f, 31.0f);
    float pf = rintf(u);
    pf = fminf(fmaxf(pf, 4.0f), 58.0f);
    int   pc = (int)pf;
    float s  = u - pf;
    s = fminf(fmaxf(s, -9.0f), 9.0f);          // avoid inf*0 at extreme inputs
    float r  = ex2f_(s * L2E);
    float E0 = ex2f_(s * s * (-0.5f * L2E));
    float q  = rcpf_(r);
    float r2 = r*r, r3 = r2*r, r4 = r2*r2;
    float q2 = q*q, q3 = q2*q, q4 = q2*q2;
    float m, A, B;
    m = w[pc-4]*(CJ4*q4); A  = m;  B = m * -4.0f;
    m = w[pc-3]*(CJ3*q3); A += m;  B = fmaf(m, -3.0f, B);
    m = w[pc-2]*(CJ2*q2); A += m;  B = fmaf(m, -2.0f, B);
    m = w[pc-1]*(CJ1*q ); A += m;  B = fmaf(m, -1.0f, B);
    m = w[pc  ];          A += m;
    m = w[pc+1]*(CJ1*r ); A += m;  B = fmaf(m,  1.0f, B);
    m = w[pc+2]*(CJ2*r2); A += m;  B = fmaf(m,  2.0f, B);
    m = w[pc+3]*(CJ3*r3); A += m;  B = fmaf(m,  3.0f, B);
    m = w[pc+4]*(CJ4*r4); A += m;  B = fmaf(m,  4.0f, B);
    a_out = E0 * A;
    g_out = (-0.1f * E0) * fmaf(s, A, -B);
}

// K1: c0 = conv5x5(rep_pad(255x), f0)+b0 ; a0 = act(c0,w0), g0 = gradact(c0,w0)
__global__ void k1_conv0_act(const float* __restrict__ x,
                             const float* __restrict__ w0) {
    __shared__ float sw0[16*63];
    int tid = threadIdx.x;
    int cbase = blockIdx.y * 16;
    for (int i = tid; i < 16*63; i += 256) sw0[i] = w0[cbase*63 + i];
    __syncthreads();

    int b = blockIdx.z;
    int p = blockIdx.x * 256 + tid;
    int h = p >> 7, w = p & 127;
    const float* xb = x + b*HW;

    float xn[25];
    #pragma unroll
    for (int dy = 0; dy < 5; ++dy) {
        int ih = min(max(h + dy - 2, 0), Hn-1);
        #pragma unroll
        for (int dx = 0; dx < 5; ++dx) {
            int iw = min(max(w + dx - 2, 0), Wn-1);
            xn[dy*5+dx] = xb[ih*Wn + iw] * 255.0f;
        }
    }
    #pragma unroll 1
    for (int cc = 0; cc < 16; ++cc) {
        int c = cbase + cc;
        float acc = c_b0[c];
        #pragma unroll
        for (int k = 0; k < 25; ++k) acc = fmaf(xn[k], c_f0[c*25 + k], acc);
        float a, g;
        rbf9(acc, &sw0[cc*63], a, g);
        int idx = (b*Cn + c)*HW + p;
        g_a0[idx] = a;
        g_g0[idx] = g;
    }
}

// K2a: 64->1 conv partials over 8-channel groups; 64x16 tile, 4-px strips.
__global__ void k2a_conv64to1() {
    __shared__ float tile[20][68];
    int tid = threadIdx.x;
    int tx = tid & 15, ty = tid >> 4;
    int b  = blockIdx.z & 3;
    int g  = blockIdx.z >> 2;
    int h0 = blockIdx.y * 16;
    int w0 = blockIdx.x * 64;
    const float* sb = g_a0 + (size_t)(b*Cn + g*8)*HW;

    float acc0 = 0.f, acc1 = 0.f, acc2 = 0.f, acc3 = 0.f;
    #pragma unroll 1
    for (int cc = 0; cc < 8; ++cc) {
        __syncthreads();
        const float* sc = sb + cc*HW;
        for (int i = tid; i < 20*68; i += 256) {
            int r  = i / 68;
            int cx = i - r*68;
            int gh = min(max(h0 + r - 2, 0), Hn-1);
            int gw = min(max(w0 + cx - 2, 0), Wn-1);
            (&tile[0][0])[i] = sc[gh*Wn + gw];
        }
        __syncthreads();
        int c = g*8 + cc;
        #pragma unroll
        for (int ky = 0; ky < 5; ++ky) {
            float4 va = *(const float4*)&tile[ty + ky][tx*4];
            float4 vb = *(const float4*)&tile[ty + ky][tx*4 + 4];
            float v[8] = {va.x, va.y, va.z, va.w, vb.x, vb.y, vb.z, vb.w};
            #pragma unroll
            for (int kx = 0; kx < 5; ++kx) {
                float f = c_f1[c*25 + ky*5 + kx];
                acc0 = fmaf(v[kx+0], f, acc0);
                acc1 = fmaf(v[kx+1], f, acc1);
                acc2 = fmaf(v[kx+2], f, acc2);
                acc3 = fmaf(v[kx+3], f, acc3);
            }
        }
    }
    *(float4*)&g_part[(size_t)g*(Bn*HW) + b*HW + (h0+ty)*Wn + w0 + tx*4]
        = make_float4(acc0, acc1, acc2, acc3);
}

// K2b: a1 = act(sum(partials) + b1, w1)
__global__ void k2b_reduce_act(const float* __restrict__ w1) {
    __shared__ float sw[Pn];
    int tid = threadIdx.x;
    if (tid < Pn) sw[tid] = w1[tid];
    __syncthreads();
    int p = blockIdx.x * 256 + tid;
    float s = c_b1[0];
    #pragma unroll
    for (int g = 0; g < 8; ++g) s += g_part[g*(Bn*HW) + p];
    float a, gr;
    rbf9(s, sw, a, gr);
    g_a1[p] = a;
}

// K5 (fused K3+K4a): per CTA / channel-group:
//   stage a1 tile in smem; per channel c: d = deconv1(a1)[c]*g0[c] tile in smem,
//   then accumulate deconv0 (flipped f0) into register strip partials.
__global__ void k5_fused_deconv() {
    __shared__ float sa1[24][72];   // rows h0-4..h0+19, cols w0-4..w0+67 (zero pad)
    __shared__ float sd[20][68];    // rows h0-2..h0+17, cols w0-2..w0+65
    int tid = threadIdx.x;
    int tx = tid & 15, ty = tid >> 4;
    int b  = blockIdx.z & 3;
    int g  = blockIdx.z >> 2;
    int h0 = blockIdx.y * 16;
    int w0 = blockIdx.x * 64;
    const float* ab = g_a1 + b*HW;

    for (int i = tid; i < 24*72; i += 256) {
        int r = i / 72, cx = i - r*72;
        int gh = h0 + r - 4, gw = w0 + cx - 4;
        (&sa1[0][0])[i] = ((unsigned)gh < (unsigned)Hn && (unsigned)gw < (unsigned)Wn)
                          ? ab[gh*Wn + gw] : 0.f;
    }

    float acc0 = 0.f, acc1 = 0.f, acc2 = 0.f, acc3 = 0.f;
    #pragma unroll 1
    for (int cc = 0; cc < 8; ++cc) {
        int c = g*8 + cc;
        const float* g0c = g_g0 + (size_t)(b*Cn + c)*HW;
        __syncthreads();
        // d tile: 20 rows x 17 strips of 4 px = 340 units
        #pragma unroll 1
        for (int u = tid; u < 340; u += 256) {
            int r = u / 17, st = u - r*17;
            int cx0 = st * 4;
            int gh = h0 + r - 2;
            float d0 = 0.f, d1 = 0.f, d2 = 0.f, d3 = 0.f;
            #pragma unroll
            for (int ky = 0; ky < 5; ++ky) {
                float4 va = *(const float4*)&sa1[r + ky][cx0];
                float4 vb = *(const float4*)&sa1[r + ky][cx0 + 4];
                float v[8] = {va.x, va.y, va.z, va.w, vb.x, vb.y, vb.z, vb.w};
                #pragma unroll
                for (int kx = 0; kx < 5; ++kx) {
                    float f = c_f1[c*25 + 24 - (ky*5 + kx)];
                    d0 = fmaf(v[kx+0], f, d0);
                    d1 = fmaf(v[kx+1], f, d1);
                    d2 = fmaf(v[kx+2], f, d2);
                    d3 = fmaf(v[kx+3], f, d3);
                }
            }
            bool rv = (unsigned)gh < (unsigned)Hn;
            int gw0 = w0 + cx0 - 2;
            const float* g0r = g0c + gh*Wn;
            d0 = (rv && (unsigned)(gw0+0) < (unsigned)Wn) ? d0 * g0r[gw0+0] : 0.f;
            d1 = (rv && (unsigned)(gw0+1) < (unsigned)Wn) ? d1 * g0r[gw0+1] : 0.f;
            d2 = (rv && (unsigned)(gw0+2) < (unsigned)Wn) ? d2 * g0r[gw0+2] : 0.f;
            d3 = (rv && (unsigned)(gw0+3) < (unsigned)Wn) ? d3 * g0r[gw0+3] : 0.f;
            *(float4*)&sd[r][cx0] = make_float4(d0, d1, d2, d3);
        }
        __syncthreads();
        // deconv0 accumulate (flipped f0)
        #pragma unroll
        for (int ky = 0; ky < 5; ++ky) {
            float4 va = *(const float4*)&sd[ty + ky][tx*4];
            float4 vb = *(const float4*)&sd[ty + ky][tx*4 + 4];
            float v[8] = {va.x, va.y, va.z, va.w, vb.x, vb.y, vb.z, vb.w};
            #pragma unroll
            for (int kx = 0; kx < 5; ++kx) {
                float f = c_f0[c*25 + 24 - (ky*5 + kx)];
                acc0 = fmaf(v[kx+0], f, acc0);
                acc1 = fmaf(v[kx+1], f, acc1);
                acc2 = fmaf(v[kx+2], f, acc2);
                acc3 = fmaf(v[kx+3], f, acc3);
            }
        }
    }
    *(float4*)&g_part[(size_t)g*(Bn*HW) + b*HW + (h0+ty)*Wn + w0 + tx*4]
        = make_float4(acc0, acc1, acc2, acc3);
}

// K4b: out = x - sum(partials)/255 - exp(lam)*(x - y)
__global__ void k4b_reduce_out(const float* __restrict__ x,
                               const float* __restrict__ y,
                               const float* __restrict__ lam_param,
                               float* __restrict__ out) {
    int p = blockIdx.x * 256 + threadIdx.x;
    float s = 0.f;
    #pragma unroll
    for (int g = 0; g < 8; ++g) s += g_part[g*(Bn*HW) + p];
    float e  = __expf(lam_param[0]);
    float xv = x[p], yv = y[p];
    out[p] = xv - s*(1.0f/255.0f) - e*(xv - yv);
}

extern "C" void kernel_launch(void* const* d_in, const int* in_sizes, int n_in,
                              void* d_out, int out_size) {
    const float* x   = (const float*)d_in[0];
    const float* y   = (const float*)d_in[1];
    // d_in[2] = lam (ignored)
    const float* f0  = (const float*)d_in[3];
    const float* b0  = (const float*)d_in[4];
    const float* f1  = (const float*)d_in[5];
    const float* b1  = (const float*)d_in[6];
    const float* w0  = (const float*)d_in[7];
    const float* w1  = (const float*)d_in[8];
    const float* lam = (const float*)d_in[9];
    float* out = (float*)d_out;

    cudaMemcpyToSymbolAsync(c_f0, f0, Cn*25*sizeof(float), 0, cudaMemcpyDeviceToDevice, 0);
    cudaMemcpyToSymbolAsync(c_f1, f1, Cn*25*sizeof(float), 0, cudaMemcpyDeviceToDevice, 0);
    cudaMemcpyToSymbolAsync(c_b0, b0, Cn*sizeof(float),    0, cudaMemcpyDeviceToDevice, 0);
    cudaMemcpyToSymbolAsync(c_b1, b1, sizeof(float),       0, cudaMemcpyDeviceToDevice, 0);

    dim3 gA(HW/256, Cn/16, Bn);    // (64, 4, 4)
    dim3 gT(Wn/64, Hn/16, Bn*8);   // (2, 8, 32)
    dim3 gR(Bn*HW/256);            // (256)

    k1_conv0_act<<<gA, 256>>>(x, w0);
    k2a_conv64to1<<<gT, 256>>>();
    k2b_reduce_act<<<gR, 256>>>(w1);
    k5_fused_deconv<<<gT, 256>>>();
    k4b_reduce_out<<<gR, 256>>>(x, y, lam, out);
}

// round 4
// speedup vs baseline: 2.1680x; 1.3703x over previous
#include <cuda_runtime.h>
#include <math.h>

#define Bn 4
#define Cn 64
#define Hn 128
#define Wn 128
#define Pn 63
#define HW (Hn*Wn)
#define NG 16   /* channel groups of 4 */

// Scratch (static device globals)
__device__ float g_g0[Bn*Cn*HW];     // grad-act(c0)
__device__ float g_a1[Bn*HW];        // act(c1)
__device__ float g_part[NG*Bn*HW];   // channel-group partial sums

__constant__ float c_f0[Cn*25];
__constant__ float c_f1[Cn*25];
__constant__ float c_b0[Cn];
__constant__ float c_b1[1];

__device__ __forceinline__ float ex2f_(float x){ float r; asm("ex2.approx.f32 %0,%1;" : "=f"(r) : "f"(x)); return r; }
__device__ __forceinline__ float rcpf_(float x){ float r; asm("rcp.approx.f32 %0,%1;" : "=f"(r) : "f"(x)); return r; }

#define CJ1 0.60653065971f
#define CJ2 0.13533528324f
#define CJ3 0.01110899654f
#define CJ4 0.00033546262f
#define L2E 1.44269504089f

// 9-tap RBF via exp decomposition: exp(-(s-j)^2/2) = E0 * r^j * c_j
__device__ __forceinline__ void rbf9(float v, const float* __restrict__ w,
                                     float& a_out, float& g_out) {
    float u  = fmaf(v, 0.1f, 31.0f);
    float pf = rintf(u);
    pf = fminf(fmaxf(pf, 4.0f), 58.0f);
    int   pc = (int)pf;
    float s  = u - pf;
    s = fminf(fmaxf(s, -9.0f), 9.0f);
    float r  = ex2f_(s * L2E);
    float E0 = ex2f_(s * s * (-0.5f * L2E));
    float q  = rcpf_(r);
    float r2 = r*r, r3 = r2*r, r4 = r2*r2;
    float q2 = q*q, q3 = q2*q, q4 = q2*q2;
    float m, A, B;
    m = w[pc-4]*(CJ4*q4); A  = m;  B = m * -4.0f;
    m = w[pc-3]*(CJ3*q3); A += m;  B = fmaf(m, -3.0f, B);
    m = w[pc-2]*(CJ2*q2); A += m;  B = fmaf(m, -2.0f, B);
    m = w[pc-1]*(CJ1*q ); A += m;  B = fmaf(m, -1.0f, B);
    m = w[pc  ];          A += m;
    m = w[pc+1]*(CJ1*r ); A += m;  B = fmaf(m,  1.0f, B);
    m = w[pc+2]*(CJ2*r2); A += m;  B = fmaf(m,  2.0f, B);
    m = w[pc+3]*(CJ3*r3); A += m;  B = fmaf(m,  3.0f, B);
    m = w[pc+4]*(CJ4*r4); A += m;  B = fmaf(m,  4.0f, B);
    a_out = E0 * A;
    g_out = (-0.1f * E0) * fmaf(s, A, -B);
}

// kA (fused K1+K2a): per CTA = 16-row full-width tile, 4 channels.
// For each channel: a0 tile (20x132, replicate-padded) in smem from conv0+rbf
// on x tile; write g0 (interior) to gmem; accumulate conv1 partials.
__global__ void __launch_bounds__(256) kA_enc(const float* __restrict__ x,
                                              const float* __restrict__ w0) {
    __shared__ float xs[24][132];    // xs[r][c] = 255*x[clamp(h0-4+r)][clamp(c-2)]
    __shared__ float sa0[20][136];   // sa0[r][c]: a0 at (h0-2+r clamped, c-2 clamped)
    __shared__ float sw0[4*63];
    int tid = threadIdx.x;
    int h0 = blockIdx.x * 16;
    int b  = blockIdx.y;
    int g  = blockIdx.z;

    for (int i = tid; i < 4*63; i += 256) sw0[i] = w0[(g*4)*63 + i];
    const float* xb = x + b*HW;
    for (int i = tid; i < 24*132; i += 256) {
        int r = i / 132, c = i - r*132;
        int gh = min(max(h0 - 4 + r, 0), Hn-1);
        int gw = min(max(c - 2, 0), Wn-1);
        (&xs[0][0])[i] = xb[gh*Wn + gw] * 255.0f;
    }

    float acc[2][4] = {{0,0,0,0},{0,0,0,0}};

    #pragma unroll 1
    for (int cc = 0; cc < 4; ++cc) {
        int c = g*4 + cc;
        float bias = c_b0[c];
        __syncthreads();
        // a0 stage: 20 rows x 32 strips of 4
        #pragma unroll 1
        for (int u = tid; u < 640; u += 256) {
            int r = u >> 5;
            int s = u & 31;
            int w = s * 4;
            int h  = min(max(h0 - 2 + r, 0), Hn-1);
            int xr = h - h0 + 2;
            float a0v = bias, a1v = bias, a2v = bias, a3v = bias;
            #pragma unroll
            for (int dy = 0; dy < 5; ++dy) {
                float4 va = *(const float4*)&xs[xr+dy][w];
                float4 vb = *(const float4*)&xs[xr+dy][w+4];
                float v[8] = {va.x, va.y, va.z, va.w, vb.x, vb.y, vb.z, vb.w};
                #pragma unroll
                for (int dx = 0; dx < 5; ++dx) {
                    float f = c_f0[c*25 + dy*5 + dx];
                    a0v = fmaf(v[dx+0], f, a0v);
                    a1v = fmaf(v[dx+1], f, a1v);
                    a2v = fmaf(v[dx+2], f, a2v);
                    a3v = fmaf(v[dx+3], f, a3v);
                }
            }
            float aa0,gg0, aa1,gg1, aa2,gg2, aa3,gg3;
            const float* wr = &sw0[cc*63];
            rbf9(a0v, wr, aa0, gg0);
            rbf9(a1v, wr, aa1, gg1);
            rbf9(a2v, wr, aa2, gg2);
            rbf9(a3v, wr, aa3, gg3);
            sa0[r][2+w+0] = aa0;
            sa0[r][2+w+1] = aa1;
            sa0[r][2+w+2] = aa2;
            sa0[r][2+w+3] = aa3;
            if (s == 0)  { sa0[r][0]   = aa0; sa0[r][1]   = aa0; }
            if (s == 31) { sa0[r][130] = aa3; sa0[r][131] = aa3; }
            if (r >= 2 && r <= 17) {
                *(float4*)&g_g0[(size_t)(b*Cn + c)*HW + (h0 + r - 2)*Wn + w]
                    = make_float4(gg0, gg1, gg2, gg3);
            }
        }
        __syncthreads();
        // conv1 accumulate: 16 rows x 32 strips = 512 units, 2 per thread
        #pragma unroll
        for (int k = 0; k < 2; ++k) {
            int u = tid + k*256;
            int r = u >> 5;
            int w = (u & 31) * 4;
            #pragma unroll
            for (int ky = 0; ky < 5; ++ky) {
                float4 va = *(const float4*)&sa0[r+ky][w];
                float4 vb = *(const float4*)&sa0[r+ky][w+4];
                float v[8] = {va.x, va.y, va.z, va.w, vb.x, vb.y, vb.z, vb.w};
                #pragma unroll
                for (int kx = 0; kx < 5; ++kx) {
                    float f = c_f1[c*25 + ky*5 + kx];
                    acc[k][0] = fmaf(v[kx+0], f, acc[k][0]);
                    acc[k][1] = fmaf(v[kx+1], f, acc[k][1]);
                    acc[k][2] = fmaf(v[kx+2], f, acc[k][2]);
                    acc[k][3] = fmaf(v[kx+3], f, acc[k][3]);
                }
            }
        }
    }
    #pragma unroll
    for (int k = 0; k < 2; ++k) {
        int u = tid + k*256;
        int r = u >> 5;
        int w = (u & 31) * 4;
        *(float4*)&g_part[(size_t)g*(Bn*HW) + b*HW + (h0+r)*Wn + w]
            = make_float4(acc[k][0], acc[k][1], acc[k][2], acc[k][3]);
    }
}

// K2b: a1 = act(sum(partials) + b1, w1)
__global__ void k2b_reduce_act(const float* __restrict__ w1) {
    __shared__ float sw[Pn];
    int tid = threadIdx.x;
    if (tid < Pn) sw[tid] = w1[tid];
    __syncthreads();
    int p = blockIdx.x * 256 + tid;
    float s = c_b1[0];
    #pragma unroll
    for (int g = 0; g < NG; ++g) s += g_part[g*(Bn*HW) + p];
    float a, gr;
    rbf9(s, sw, a, gr);
    g_a1[p] = a;
}

// K5: per CTA = 16-row full-width tile, 4 channels.
// Per channel: d tile (20x132) = deconv1(a1)*g0 in smem, then deconv0 partials.
__global__ void __launch_bounds__(256) k5_fused_deconv() {
    __shared__ float sa1[24][136];   // sa1[r][c] = a1[h0-4+r][c-4], zero pad
    __shared__ float sd[20][132];    // sd[r][c] = d[h0-2+r][c-2] (0 out of range)
    int tid = threadIdx.x;
    int h0 = blockIdx.x * 16;
    int b  = blockIdx.y;
    int g  = blockIdx.z;
    const float* ab = g_a1 + b*HW;

    for (int i = tid; i < 24*136; i += 256) {
        int r = i / 136, c = i - r*136;
        int gh = h0 - 4 + r, gw = c - 4;
        (&sa1[0][0])[i] = ((unsigned)gh < (unsigned)Hn && (unsigned)gw < (unsigned)Wn)
                          ? ab[gh*Wn + gw] : 0.f;
    }

    float acc[2][4] = {{0,0,0,0},{0,0,0,0}};

    #pragma unroll 1
    for (int cc = 0; cc < 4; ++cc) {
        int c = g*4 + cc;
        const float* g0c = g_g0 + (size_t)(b*Cn + c)*HW;
        __syncthreads();
        // d stage: 20 rows x 33 strips of 4 = 660 units
        #pragma unroll 1
        for (int u = tid; u < 660; u += 256) {
            int r  = u / 33;
            int s  = u - r*33;
            int c0 = s * 4;                   // sd col base; d col = c0-2+j
            int hd = h0 - 2 + r;
            float d0 = 0.f, d1 = 0.f, d2 = 0.f, d3 = 0.f;
            #pragma unroll
            for (int ky = 0; ky < 5; ++ky) {
                float4 va = *(const float4*)&sa1[r+ky][c0];
                float4 vb = *(const float4*)&sa1[r+ky][c0+4];
                float v[8] = {va.x, va.y, va.z, va.w, vb.x, vb.y, vb.z, vb.w};
                #pragma unroll
                for (int kx = 0; kx < 5; ++kx) {
                    float f = c_f1[c*25 + 24 - (ky*5 + kx)];
                    d0 = fmaf(v[kx+0], f, d0);
                    d1 = fmaf(v[kx+1], f, d1);
                    d2 = fmaf(v[kx+2], f, d2);
                    d3 = fmaf(v[kx+3], f, d3);
                }
            }
            bool rv = (unsigned)hd < (unsigned)Hn;
            int hs = min(max(hd, 0), Hn-1);
            const float* g0r = g0c + hs*Wn;
            int w0c = c0 - 2;
            int wa = min(max(w0c+0, 0), Wn-1);
            int wb = min(max(w0c+1, 0), Wn-1);
            int wc = min(max(w0c+2, 0), Wn-1);
            int wd = min(max(w0c+3, 0), Wn-1);
            d0 = (rv && (unsigned)(w0c+0) < (unsigned)Wn) ? d0 * g0r[wa] : 0.f;
            d1 = (rv && (unsigned)(w0c+1) < (unsigned)Wn) ? d1 * g0r[wb] : 0.f;
            d2 = (rv && (unsigned)(w0c+2) < (unsigned)Wn) ? d2 * g0r[wc] : 0.f;
            d3 = (rv && (unsigned)(w0c+3) < (unsigned)Wn) ? d3 * g0r[wd] : 0.f;
            *(float4*)&sd[r][c0] = make_float4(d0, d1, d2, d3);
        }
        __syncthreads();
        // deconv0 accumulate: 16 rows x 32 strips = 512 units
        #pragma unroll
        for (int k = 0; k < 2; ++k) {
            int u = tid + k*256;
            int r = u >> 5;
            int w = (u & 31) * 4;
            #pragma unroll
            for (int ky = 0; ky < 5; ++ky) {
                float4 va = *(const float4*)&sd[r+ky][w];
                float4 vb = *(const float4*)&sd[r+ky][w+4];
                float v[8] = {va.x, va.y, va.z, va.w, vb.x, vb.y, vb.z, vb.w};
                #pragma unroll
                for (int kx = 0; kx < 5; ++kx) {
                    float f = c_f0[c*25 + 24 - (ky*5 + kx)];
                    acc[k][0] = fmaf(v[kx+0], f, acc[k][0]);
                    acc[k][1] = fmaf(v[kx+1], f, acc[k][1]);
                    acc[k][2] = fmaf(v[kx+2], f, acc[k][2]);
                    acc[k][3] = fmaf(v[kx+3], f, acc[k][3]);
                }
            }
        }
    }
    #pragma unroll
    for (int k = 0; k < 2; ++k) {
        int u = tid + k*256;
        int r = u >> 5;
        int w = (u & 31) * 4;
        *(float4*)&g_part[(size_t)g*(Bn*HW) + b*HW + (h0+r)*Wn + w]
            = make_float4(acc[k][0], acc[k][1], acc[k][2], acc[k][3]);
    }
}

// K4b: out = x - sum(partials)/255 - exp(lam)*(x - y)
__global__ void k4b_reduce_out(const float* __restrict__ x,
                               const float* __restrict__ y,
                               const float* __restrict__ lam_param,
                               float* __restrict__ out) {
    int p = blockIdx.x * 256 + threadIdx.x;
    float s = 0.f;
    #pragma unroll
    for (int g = 0; g < NG; ++g) s += g_part[g*(Bn*HW) + p];
    float e  = __expf(lam_param[0]);
    float xv = x[p], yv = y[p];
    out[p] = xv - s*(1.0f/255.0f) - e*(xv - yv);
}

extern "C" void kernel_launch(void* const* d_in, const int* in_sizes, int n_in,
                              void* d_out, int out_size) {
    const float* x   = (const float*)d_in[0];
    const float* y   = (const float*)d_in[1];
    // d_in[2] = lam (ignored)
    const float* f0  = (const float*)d_in[3];
    const float* b0  = (const float*)d_in[4];
    const float* f1  = (const float*)d_in[5];
    const float* b1  = (const float*)d_in[6];
    const float* w0  = (const float*)d_in[7];
    const float* w1  = (const float*)d_in[8];
    const float* lam = (const float*)d_in[9];
    float* out = (float*)d_out;

    cudaMemcpyToSymbolAsync(c_f0, f0, Cn*25*sizeof(float), 0, cudaMemcpyDeviceToDevice, 0);
    cudaMemcpyToSymbolAsync(c_f1, f1, Cn*25*sizeof(float), 0, cudaMemcpyDeviceToDevice, 0);
    cudaMemcpyToSymbolAsync(c_b0, b0, Cn*sizeof(float),    0, cudaMemcpyDeviceToDevice, 0);
    cudaMemcpyToSymbolAsync(c_b1, b1, sizeof(float),       0, cudaMemcpyDeviceToDevice, 0);

    dim3 gT(Hn/16, Bn, NG);        // (8, 4, 16) = 512 CTAs
    dim3 gR(Bn*HW/256);            // (256)

    kA_enc<<<gT, 256>>>(x, w0);
    k2b_reduce_act<<<gR, 256>>>(w1);
    k5_fused_deconv<<<gT, 256>>>();
    k4b_reduce_out<<<gR, 256>>>(x, y, lam, out);
}